// round 16
// baseline (speedup 1.0000x reference)
#include <cuda_runtime.h>
#include <cuda_bf16.h>
#include <math.h>
#include <stdint.h>

// ---------------- problem constants ----------------
constexpr int B = 2, D = 32, H = 56, W = 56, C = 96;
constexpr int HEADS = 3, HD = 32;
constexpr int WD = 2, WH = 7, WWIN = 7, N = 98;     // window dims, tokens/window
constexpr int SD = 1, SH = 3, SW = 3;               // shift
constexpr int NDW = 16, NHW = 8, NWW = 8;           // windows per axis
constexpr int NW1 = NDW * NHW * NWW;                // 1024 windows per batch image
constexpr int NWIN = B * NW1;                       // 2048 windows total
constexpr int NTOK = B * D * H * W;                 // 200704 tokens
constexpr int HIDDEN = 4 * C;                       // 384
constexpr float EPS = 1e-5f;
constexpr float SCALE = 0.17677669529663687f;       // 1/sqrt(32)

// ---------------- scratch (device globals; no runtime alloc) ----------------
__device__ __nv_bfloat16 g_qkv [(size_t)NTOK * 3 * C];      // qkv (bf16, Q pre-scaled)
__device__ __nv_bfloat16 g_att [(size_t)NTOK * C];          // attn out (bf16)
__device__ float         g_x2  [(size_t)NTOK * C];          // residual trunk (fp32)
__device__ __nv_bfloat16 g_h2  [(size_t)NTOK * C];          // LN2 out (bf16)
// bf16 weights (pre-converted once per launch)
__device__ __nv_bfloat16 g_wqkv [288 * 96];                 // Q rows pre-scaled
__device__ __nv_bfloat16 g_wproj[96 * 96];
__device__ __nv_bfloat16 g_wfc1 [384 * 96];
__device__ __nv_bfloat16 g_wfc2 [96 * 384];

// ---------------- small helpers ----------------
__device__ __forceinline__ uint32_t smem_u32(const void* p) {
    return (uint32_t)__cvta_generic_to_shared(p);
}
__device__ __forceinline__ uint32_t pack_bf2(float a, float b) {
    __nv_bfloat162 h = __floats2bfloat162_rn(a, b);
    return *(uint32_t*)&h;
}
__device__ __forceinline__ void warp_reduce2(float& s, float& sq) {
    #pragma unroll
    for (int off = 16; off; off >>= 1) {
        s  += __shfl_xor_sync(0xffffffffu, s, off);
        sq += __shfl_xor_sync(0xffffffffu, sq, off);
    }
}
__device__ __forceinline__ float gelu_f(float v) {
    return 0.5f * v * (1.0f + erff(v * 0.70710678118654752f));
}

// window-row index -> BDHWC flat spatial offset (element offset of channel 0)
__device__ __forceinline__ uint32_t rowToSpatial(int r) {
    int win = r / N, n = r % N;
    int bb = win / NW1, rem = win % NW1;
    int wd = rem / (NHW * NWW), wh = (rem / NWW) % NHW, ww = rem % NWW;
    int id = n / (WH * WWIN), ih = (n / WWIN) % WH, iw = n % WWIN;
    int ds = wd * WD + id, hs = wh * WH + ih, ws = ww * WWIN + iw;
    int d = (ds + SD) % D, h = (hs + SH) % H, w = (ws + SW) % W;
    return (uint32_t)(((bb * D + d) * H + h) * W + w) * C;
}

// ---------------- weight prep: fp32 -> bf16 globals (Q rows pre-scaled) ----------------
__global__ void k_prep(const float* __restrict__ qkv_w, const float* __restrict__ proj_w,
                       const float* __restrict__ fc1_w, const float* __restrict__ fc2_w) {
    int t = blockIdx.x * 256 + threadIdx.x;
    if (t < 288 * 96) {
        float v = qkv_w[t];
        if (t < 96 * 96) v *= SCALE;
        g_wqkv[t] = __float2bfloat16(v);
    }
    if (t < 96 * 96)  g_wproj[t] = __float2bfloat16(proj_w[t]);
    if (t < 384 * 96) g_wfc1[t]  = __float2bfloat16(fc1_w[t]);
    if (t < 96 * 384) g_wfc2[t]  = __float2bfloat16(fc2_w[t]);
}

// ================= mma primitives =================
__device__ __forceinline__ void ldsm4(uint32_t& r0, uint32_t& r1,
                                      uint32_t& r2, uint32_t& r3, uint32_t addr) {
    asm volatile("ldmatrix.sync.aligned.m8n8.x4.shared.b16 {%0,%1,%2,%3}, [%4];"
                 : "=r"(r0), "=r"(r1), "=r"(r2), "=r"(r3) : "r"(addr));
}
__device__ __forceinline__ void ldsm4t(uint32_t& r0, uint32_t& r1,
                                       uint32_t& r2, uint32_t& r3, uint32_t addr) {
    asm volatile("ldmatrix.sync.aligned.m8n8.x4.trans.shared.b16 {%0,%1,%2,%3}, [%4];"
                 : "=r"(r0), "=r"(r1), "=r"(r2), "=r"(r3) : "r"(addr));
}
__device__ __forceinline__ void mma16816(float* d, const uint32_t* a, const uint32_t* b) {
    asm volatile(
        "mma.sync.aligned.m16n8k16.row.col.f32.bf16.bf16.f32 "
        "{%0,%1,%2,%3}, {%4,%5,%6,%7}, {%8,%9}, {%0,%1,%2,%3};"
        : "+f"(d[0]), "+f"(d[1]), "+f"(d[2]), "+f"(d[3])
        : "r"(a[0]), "r"(a[1]), "r"(a[2]), "r"(a[3]), "r"(b[0]), "r"(b[1]));
}

constexpr int SA = 104;            // padded bf16 row stride (208B)

// B tile stage from bf16 source (pure copy): 96 rows x 96 bf16
__device__ __forceinline__ void stageBbf(__nv_bfloat16* Bs, const __nv_bfloat16* __restrict__ src,
                                         int strideElems, int tid) {
    for (int idx = tid; idx < 96 * 12; idx += 256) {
        int row = idx / 12, c8 = idx % 12;
        *(uint4*)&Bs[row * SA + c8 * 8] =
            *(const uint4*)(src + (size_t)row * strideElems + c8 * 8);
    }
}

// ================= LN1 + qkv fused (M=128, 3 column tiles in-CTA) =================
__global__ void __launch_bounds__(256) k_qkvln(const float* __restrict__ x,
                                               const float* __restrict__ n1g,
                                               const float* __restrict__ n1b,
                                               const float* __restrict__ bias,
                                               __nv_bfloat16* __restrict__ Cout) {
    __shared__ __nv_bfloat16 As[128 * SA];
    __shared__ __nv_bfloat16 Bs[96 * SA];
    __shared__ uint32_t soffS[128];
    int tid = threadIdx.x;
    int wid = tid >> 5, lane = tid & 31;
    int wm = wid & 3, wn = wid >> 2;
    int rowBase = blockIdx.x * 128;

    if (tid < 128) soffS[tid] = rowToSpatial(rowBase + tid);
    __syncthreads();

    // LN1: warp per row (gather + normalize -> As bf16)
    for (int r = wid; r < 128; r += 8) {
        const float* src = x + soffS[r];
        float v0 = src[lane], v1 = src[lane + 32], v2 = src[lane + 64];
        float s = v0 + v1 + v2, sq = v0 * v0 + v1 * v1 + v2 * v2;
        warp_reduce2(s, sq);
        float mean = s * (1.0f / 96.0f);
        float var  = sq * (1.0f / 96.0f) - mean * mean;
        float rr = rsqrtf(var + EPS);
        As[r * SA + lane]      = __float2bfloat16((v0 - mean) * rr * n1g[lane]      + n1b[lane]);
        As[r * SA + lane + 32] = __float2bfloat16((v1 - mean) * rr * n1g[lane + 32] + n1b[lane + 32]);
        As[r * SA + lane + 64] = __float2bfloat16((v2 - mean) * rr * n1g[lane + 64] + n1b[lane + 64]);
    }

    uint32_t a_addr[2], b_addr[3];
    {
        int ar = (lane & 15), ac = (lane >> 4) * 8;
        #pragma unroll
        for (int mt = 0; mt < 2; mt++)
            a_addr[mt] = smem_u32(&As[(wm * 32 + mt * 16 + ar) * SA + ac]);
        int br = (lane >> 4) * 8 + (lane & 7), bc = ((lane >> 3) & 1) * 8;
        #pragma unroll
        for (int p = 0; p < 3; p++)
            b_addr[p] = smem_u32(&Bs[(wn * 48 + p * 16 + br) * SA + bc]);
    }
    int colq = (lane & 3) * 2, rq = lane >> 2;

    for (int ct = 0; ct < 3; ct++) {
        float bsc = (ct == 0) ? SCALE : 1.0f;
        __syncthreads();
        stageBbf(Bs, g_wqkv + (size_t)ct * 96 * 96, 96, tid);
        __syncthreads();

        float acc[2][6][4];
        #pragma unroll
        for (int i = 0; i < 2; i++)
            #pragma unroll
            for (int j = 0; j < 6; j++)
                #pragma unroll
                for (int e = 0; e < 4; e++) acc[i][j][e] = 0.0f;
        #pragma unroll
        for (int ks = 0; ks < 6; ks++) {
            uint32_t a[2][4], b[6][2];
            #pragma unroll
            for (int mt = 0; mt < 2; mt++)
                ldsm4(a[mt][0], a[mt][1], a[mt][2], a[mt][3], a_addr[mt] + ks * 32);
            #pragma unroll
            for (int p = 0; p < 3; p++)
                ldsm4(b[2 * p][0], b[2 * p][1], b[2 * p + 1][0], b[2 * p + 1][1],
                      b_addr[p] + ks * 32);
            #pragma unroll
            for (int mt = 0; mt < 2; mt++)
                #pragma unroll
                for (int nt = 0; nt < 6; nt++)
                    mma16816(acc[mt][nt], a[mt], b[nt]);
        }
        #pragma unroll
        for (int mt = 0; mt < 2; mt++)
            #pragma unroll
            for (int half = 0; half < 2; half++) {
                int row = rowBase + wm * 32 + mt * 16 + half * 8 + rq;
                #pragma unroll
                for (int nt = 0; nt < 6; nt++) {
                    int col = wn * 48 + nt * 8 + colq;
                    float2 bv = *(const float2*)(bias + ct * 96 + col);
                    float ox = acc[mt][nt][half * 2 + 0] + bv.x * bsc;
                    float oy = acc[mt][nt][half * 2 + 1] + bv.y * bsc;
                    *(uint32_t*)(Cout + (size_t)row * 288 + ct * 96 + col) = pack_bf2(ox, oy);
                }
            }
    }
}

// ================= proj + scatter residual + LN2 fused (M=64) =================
__global__ void __launch_bounds__(256) k_proj(const __nv_bfloat16* __restrict__ A,
                                              const float* __restrict__ bias,
                                              const float* __restrict__ x,
                                              float* __restrict__ x2,
                                              __nv_bfloat16* __restrict__ h2,
                                              const float* __restrict__ n2g,
                                              const float* __restrict__ n2b) {
    __shared__ __nv_bfloat16 As[64 * SA];
    __shared__ __nv_bfloat16 Bs[96 * SA];
    __shared__ __nv_bfloat16 X2s[64 * 96];
    __shared__ uint32_t soffS[64];
    int tid = threadIdx.x;
    int wid = tid >> 5, lane = tid & 31;
    int wm = wid & 3, wn = wid >> 2;
    int rowBase = blockIdx.x * 64;

    #pragma unroll
    for (int it = 0; it < 3; it++) {
        int idx = tid + it * 256;
        int row = idx / 12, c8 = idx % 12;
        uint4 v = *(const uint4*)(A + (size_t)(rowBase + row) * 96 + c8 * 8);
        *(uint4*)&As[row * SA + c8 * 8] = v;
    }
    stageBbf(Bs, g_wproj, 96, tid);
    if (tid < 64) soffS[tid] = rowToSpatial(rowBase + tid);
    __syncthreads();

    uint32_t a_addr, b_addr[3];
    {
        int ar = (lane & 15), ac = (lane >> 4) * 8;
        a_addr = smem_u32(&As[(wm * 16 + ar) * SA + ac]);
        int br = (lane >> 4) * 8 + (lane & 7), bc = ((lane >> 3) & 1) * 8;
        #pragma unroll
        for (int p = 0; p < 3; p++)
            b_addr[p] = smem_u32(&Bs[(wn * 48 + p * 16 + br) * SA + bc]);
    }
    float acc[6][4];
    #pragma unroll
    for (int j = 0; j < 6; j++)
        #pragma unroll
        for (int e = 0; e < 4; e++) acc[j][e] = 0.0f;
    #pragma unroll
    for (int ks = 0; ks < 6; ks++) {
        uint32_t a[4], b[6][2];
        ldsm4(a[0], a[1], a[2], a[3], a_addr + ks * 32);
        #pragma unroll
        for (int p = 0; p < 3; p++)
            ldsm4(b[2 * p][0], b[2 * p][1], b[2 * p + 1][0], b[2 * p + 1][1],
                  b_addr[p] + ks * 32);
        #pragma unroll
        for (int nt = 0; nt < 6; nt++)
            mma16816(acc[nt], a, b[nt]);
    }

    int colq = (lane & 3) * 2, rq = lane >> 2;
    #pragma unroll
    for (int half = 0; half < 2; half++) {
        int lrow = wm * 16 + half * 8 + rq;
        uint32_t soff = soffS[lrow];
        #pragma unroll
        for (int nt = 0; nt < 6; nt++) {
            int col = wn * 48 + nt * 8 + colq;
            float2 bv = *(const float2*)(bias + col);
            float2 rv = *(const float2*)(x + soff + col);
            float ox = acc[nt][half * 2 + 0] + bv.x + rv.x;
            float oy = acc[nt][half * 2 + 1] + bv.y + rv.y;
            *(float2*)(x2 + soff + col) = make_float2(ox, oy);
            *(uint32_t*)&X2s[lrow * 96 + col] = pack_bf2(ox, oy);
        }
    }
    __syncthreads();

    // LN2 over the 64 rows (warp per row)
    for (int r = wid; r < 64; r += 8) {
        float v0 = __bfloat162float(X2s[r * 96 + lane]);
        float v1 = __bfloat162float(X2s[r * 96 + lane + 32]);
        float v2 = __bfloat162float(X2s[r * 96 + lane + 64]);
        float s = v0 + v1 + v2, sq = v0 * v0 + v1 * v1 + v2 * v2;
        warp_reduce2(s, sq);
        float mean = s * (1.0f / 96.0f);
        float var  = sq * (1.0f / 96.0f) - mean * mean;
        float rr = rsqrtf(var + EPS);
        __nv_bfloat16* dst = h2 + soffS[r];
        dst[lane]      = __float2bfloat16((v0 - mean) * rr * n2g[lane]      + n2b[lane]);
        dst[lane + 32] = __float2bfloat16((v1 - mean) * rr * n2g[lane + 32] + n2b[lane + 32]);
        dst[lane + 64] = __float2bfloat16((v2 - mean) * rr * n2g[lane + 64] + n2b[lane + 64]);
    }
}

// ================= fused MLP: fc1 + GELU + fc2 + residual (M=128, dyn smem) =================
__global__ void __launch_bounds__(256) k_mlp(const __nv_bfloat16* __restrict__ A,
                                             const float* __restrict__ b1,
                                             const float* __restrict__ b2,
                                             const float* __restrict__ x2,
                                             float* __restrict__ out) {
    extern __shared__ __nv_bfloat16 dyn[];
    __nv_bfloat16* As = dyn;                 // 128*SA
    __nv_bfloat16* Hs = dyn + 128 * SA;      // 128*SA
    __nv_bfloat16* Bs = dyn + 256 * SA;      // 96*SA
    int tid = threadIdx.x;
    int wid = tid >> 5, lane = tid & 31;
    int wm = wid & 3, wn = wid >> 2;
    int rowBase = blockIdx.x * 128;

    for (int idx = tid; idx < 128 * 12; idx += 256) {
        int row = idx / 12, c8 = idx % 12;
        *(uint4*)&As[row * SA + c8 * 8] =
            *(const uint4*)(A + (size_t)(rowBase + row) * 96 + c8 * 8);
    }

    uint32_t a_addr[2], h_addr[2], b_addr[3];
    {
        int ar = (lane & 15), ac = (lane >> 4) * 8;
        #pragma unroll
        for (int mt = 0; mt < 2; mt++) {
            a_addr[mt] = smem_u32(&As[(wm * 32 + mt * 16 + ar) * SA + ac]);
            h_addr[mt] = smem_u32(&Hs[(wm * 32 + mt * 16 + ar) * SA + ac]);
        }
        int br = (lane >> 4) * 8 + (lane & 7), bc = ((lane >> 3) & 1) * 8;
        #pragma unroll
        for (int p = 0; p < 3; p++)
            b_addr[p] = smem_u32(&Bs[(wn * 48 + p * 16 + br) * SA + bc]);
    }
    int colq = (lane & 3) * 2, rq = lane >> 2;

    float oacc[2][6][4];
    #pragma unroll
    for (int i = 0; i < 2; i++)
        #pragma unroll
        for (int j = 0; j < 6; j++)
            #pragma unroll
            for (int e = 0; e < 4; e++) oacc[i][j][e] = 0.0f;

    for (int hc = 0; hc < 4; hc++) {
        __syncthreads();
        stageBbf(Bs, g_wfc1 + (size_t)hc * 96 * 96, 96, tid);
        __syncthreads();
        // fc1 partial
        float hacc[2][6][4];
        #pragma unroll
        for (int i = 0; i < 2; i++)
            #pragma unroll
            for (int j = 0; j < 6; j++)
                #pragma unroll
                for (int e = 0; e < 4; e++) hacc[i][j][e] = 0.0f;
        #pragma unroll
        for (int ks = 0; ks < 6; ks++) {
            uint32_t a[2][4], b[6][2];
            #pragma unroll
            for (int mt = 0; mt < 2; mt++)
                ldsm4(a[mt][0], a[mt][1], a[mt][2], a[mt][3], a_addr[mt] + ks * 32);
            #pragma unroll
            for (int p = 0; p < 3; p++)
                ldsm4(b[2 * p][0], b[2 * p][1], b[2 * p + 1][0], b[2 * p + 1][1],
                      b_addr[p] + ks * 32);
            #pragma unroll
            for (int mt = 0; mt < 2; mt++)
                #pragma unroll
                for (int nt = 0; nt < 6; nt++)
                    mma16816(hacc[mt][nt], a[mt], b[nt]);
        }
        // bias + GELU -> Hs
        #pragma unroll
        for (int mt = 0; mt < 2; mt++)
            #pragma unroll
            for (int half = 0; half < 2; half++) {
                int lrow = wm * 32 + mt * 16 + half * 8 + rq;
                #pragma unroll
                for (int nt = 0; nt < 6; nt++) {
                    int col = wn * 48 + nt * 8 + colq;
                    float2 bv = *(const float2*)(b1 + hc * 96 + col);
                    float gx = gelu_f(hacc[mt][nt][half * 2 + 0] + bv.x);
                    float gy = gelu_f(hacc[mt][nt][half * 2 + 1] + bv.y);
                    *(uint32_t*)&Hs[lrow * SA + col] = pack_bf2(gx, gy);
                }
            }
        __syncthreads();
        stageBbf(Bs, g_wfc2 + (size_t)hc * 96, 384, tid);
        __syncthreads();
        // fc2 partial
        #pragma unroll
        for (int ks = 0; ks < 6; ks++) {
            uint32_t a[2][4], b[6][2];
            #pragma unroll
            for (int mt = 0; mt < 2; mt++)
                ldsm4(a[mt][0], a[mt][1], a[mt][2], a[mt][3], h_addr[mt] + ks * 32);
            #pragma unroll
            for (int p = 0; p < 3; p++)
                ldsm4(b[2 * p][0], b[2 * p][1], b[2 * p + 1][0], b[2 * p + 1][1],
                      b_addr[p] + ks * 32);
            #pragma unroll
            for (int mt = 0; mt < 2; mt++)
                #pragma unroll
                for (int nt = 0; nt < 6; nt++)
                    mma16816(oacc[mt][nt], a[mt], b[nt]);
        }
    }

    // epilogue: + b2 + x2 residual -> out
    #pragma unroll
    for (int mt = 0; mt < 2; mt++)
        #pragma unroll
        for (int half = 0; half < 2; half++) {
            int row = rowBase + wm * 32 + mt * 16 + half * 8 + rq;
            #pragma unroll
            for (int nt = 0; nt < 6; nt++) {
                int col = wn * 48 + nt * 8 + colq;
                float2 bv = *(const float2*)(b2 + col);
                float2 rv = *(const float2*)(x2 + (size_t)row * 96 + col);
                float ox = oacc[mt][nt][half * 2 + 0] + bv.x + rv.x;
                float oy = oacc[mt][nt][half * 2 + 1] + bv.y + rv.y;
                *(float2*)(out + (size_t)row * 96 + col) = make_float2(ox, oy);
            }
        }
}

// ================= tensor-core windowed attention (bf16 qkv in, bf16 out) =================
constexpr int SAT = 40;   // bf16 row stride (80B) for Q/K/V smem

__global__ void __launch_bounds__(128) k_attn(int dummy) {
    __shared__ __nv_bfloat16 Qs[112 * SAT];
    __shared__ __nv_bfloat16 Ks[112 * SAT];
    __shared__ __nv_bfloat16 Vs[112 * SAT];
    __shared__ int clsS[112];

    int win = blockIdx.x, h = blockIdx.y;
    int tid = threadIdx.x, wid = tid >> 5, lane = tid & 31;
    const __nv_bfloat16* base = g_qkv + (size_t)win * N * (3 * C);

    int rem = win % NW1;
    int wd = rem / (NHW * NWW), wh = (rem / NWW) % NHW, ww = rem % NWW;
    if (tid < 112) {
        int cls = 255;
        if (tid < N) {
            int id = tid / 49, ih = (tid / 7) % 7, iw = tid % 7;
            int ds = wd * WD + id, hs = wh * WH + ih, ws = ww * WWIN + iw;
            int cd = (ds < D - WD) ? 0 : ((ds < D - SD) ? 1 : 2);
            int ch = (hs < H - WH) ? 0 : ((hs < H - SH) ? 1 : 2);
            int cw = (ws < W - WWIN) ? 0 : ((ws < W - SW) ? 1 : 2);
            cls = cd * 9 + ch * 3 + cw;
        }
        clsS[tid] = cls;
    }
    for (int idx = tid; idx < 112 * 4; idx += 128) {
        int row = idx >> 2, seg = idx & 3;
        uint4 q = make_uint4(0, 0, 0, 0), k = q, v = q;
        if (row < N) {
            const uint4* rp = (const uint4*)(base + (size_t)row * (3 * C));
            q = rp[h * 4 + seg];
            k = rp[12 + h * 4 + seg];
            v = rp[24 + h * 4 + seg];
        }
        *(uint4*)&Qs[row * SAT + seg * 8] = q;
        *(uint4*)&Ks[row * SAT + seg * 8] = k;
        *(uint4*)&Vs[row * SAT + seg * 8] = v;
    }
    __syncthreads();

    int r16 = lane & 15, g8 = (lane >> 4) * 8;
    int quad = lane >> 2, tq = lane & 3;

    for (int mt = wid; mt < 7; mt += 4) {
        uint32_t aq[2][4];
        uint32_t qaddr = smem_u32(&Qs[(mt * 16 + r16) * SAT + g8]);
        ldsm4(aq[0][0], aq[0][1], aq[0][2], aq[0][3], qaddr);
        ldsm4(aq[1][0], aq[1][1], aq[1][2], aq[1][3], qaddr + 32);

        float s[13][4];
        #pragma unroll
        for (int nt = 0; nt < 13; nt++)
            #pragma unroll
            for (int e = 0; e < 4; e++) s[nt][e] = 0.0f;
        #pragma unroll
        for (int ntp = 0; ntp < 7; ntp++) {
            uint32_t kaddr = smem_u32(&Ks[(ntp * 16 + r16) * SAT + g8]);
            uint32_t lo0, lo1, lo2, lo3, hi0, hi1, hi2, hi3;
            ldsm4(lo0, lo1, lo2, lo3, kaddr);
            ldsm4(hi0, hi1, hi2, hi3, kaddr + 32);
            uint32_t b0[2] = {lo0, lo2}, b0h[2] = {hi0, hi2};
            mma16816(s[2 * ntp], aq[0], b0);
            mma16816(s[2 * ntp], aq[1], b0h);
            if (2 * ntp + 1 < 13) {
                uint32_t b1[2] = {lo1, lo3}, b1h[2] = {hi1, hi3};
                mma16816(s[2 * ntp + 1], aq[0], b1);
                mma16816(s[2 * ntp + 1], aq[1], b1h);
            }
        }

        int i0cls = clsS[mt * 16 + quad];
        int i1cls = clsS[mt * 16 + 8 + quad];
        float sum0 = 0.0f, sum1 = 0.0f;
        uint32_t pk[14][2];
        #pragma unroll
        for (int nt = 0; nt < 13; nt++) {
            int col0 = nt * 8 + tq * 2;
            int mc0 = clsS[col0], mc1 = clsS[col0 + 1];
            float p00 = __expf(s[nt][0] + ((mc0 == i0cls) ? 0.0f : -100.0f));
            float p01 = __expf(s[nt][1] + ((mc1 == i0cls) ? 0.0f : -100.0f));
            float p10 = __expf(s[nt][2] + ((mc0 == i1cls) ? 0.0f : -100.0f));
            float p11 = __expf(s[nt][3] + ((mc1 == i1cls) ? 0.0f : -100.0f));
            if (nt == 12) {
                if (col0 >= N)     { p00 = 0.0f; p10 = 0.0f; }
                if (col0 + 1 >= N) { p01 = 0.0f; p11 = 0.0f; }
            }
            sum0 += p00 + p01; sum1 += p10 + p11;
            pk[nt][0] = pack_bf2(p00, p01);
            pk[nt][1] = pack_bf2(p10, p11);
        }
        pk[13][0] = 0; pk[13][1] = 0;
        sum0 += __shfl_xor_sync(0xffffffffu, sum0, 1);
        sum0 += __shfl_xor_sync(0xffffffffu, sum0, 2);
        sum1 += __shfl_xor_sync(0xffffffffu, sum1, 1);
        sum1 += __shfl_xor_sync(0xffffffffu, sum1, 2);

        float o[4][4];
        #pragma unroll
        for (int nt = 0; nt < 4; nt++)
            #pragma unroll
            for (int e = 0; e < 4; e++) o[nt][e] = 0.0f;
        #pragma unroll
        for (int s7 = 0; s7 < 7; s7++) {
            uint32_t a[4] = {pk[2 * s7][0], pk[2 * s7][1],
                             pk[2 * s7 + 1][0], pk[2 * s7 + 1][1]};
            uint32_t vaddr = smem_u32(&Vs[(s7 * 16 + r16) * SAT + g8]);
            uint32_t v0, v1, v2, v3, v4, v5, v6, v7;
            ldsm4t(v0, v1, v2, v3, vaddr);
            ldsm4t(v4, v5, v6, v7, vaddr + 32);
            uint32_t bt0[2] = {v0, v1}, bt1[2] = {v2, v3};
            uint32_t bt2[2] = {v4, v5}, bt3[2] = {v6, v7};
            mma16816(o[0], a, bt0);
            mma16816(o[1], a, bt1);
            mma16816(o[2], a, bt2);
            mma16816(o[3], a, bt3);
        }

        float inv0 = 1.0f / sum0, inv1 = 1.0f / sum1;
        int i0 = mt * 16 + quad, i1 = i0 + 8;
        if (i0 < N) {
            __nv_bfloat16* op = g_att + ((size_t)win * N + i0) * C + h * HD + tq * 2;
            #pragma unroll
            for (int nt = 0; nt < 4; nt++)
                *(uint32_t*)(op + nt * 8) = pack_bf2(o[nt][0] * inv0, o[nt][1] * inv0);
        }
        if (i1 < N) {
            __nv_bfloat16* op = g_att + ((size_t)win * N + i1) * C + h * HD + tq * 2;
            #pragma unroll
            for (int nt = 0; nt < 4; nt++)
                *(uint32_t*)(op + nt * 8) = pack_bf2(o[nt][2] * inv1, o[nt][3] * inv1);
        }
    }
}

// ---------------- launch ----------------
extern "C" void kernel_launch(void* const* d_in, const int* in_sizes, int n_in,
                              void* d_out, int out_size) {
    const float* x       = (const float*)d_in[0];
    const float* n1g     = (const float*)d_in[2];
    const float* n1b     = (const float*)d_in[3];
    const float* qkv_w   = (const float*)d_in[4];
    const float* qkv_b   = (const float*)d_in[5];
    const float* proj_w  = (const float*)d_in[6];
    const float* proj_b  = (const float*)d_in[7];
    const float* n2g     = (const float*)d_in[8];
    const float* n2b     = (const float*)d_in[9];
    const float* fc1_w   = (const float*)d_in[10];
    const float* fc1_b   = (const float*)d_in[11];
    const float* fc2_w   = (const float*)d_in[12];
    const float* fc2_b   = (const float*)d_in[13];
    float* out = (float*)d_out;

    __nv_bfloat16* p_qkv; cudaGetSymbolAddress((void**)&p_qkv, g_qkv);
    __nv_bfloat16* p_att; cudaGetSymbolAddress((void**)&p_att, g_att);
    float*         p_x2;  cudaGetSymbolAddress((void**)&p_x2,  g_x2);
    __nv_bfloat16* p_h2;  cudaGetSymbolAddress((void**)&p_h2,  g_h2);

    constexpr int MLP_SMEM = (256 * SA + 96 * SA) * 2;   // 73216 bytes
    static bool attr_set = false;
    if (!attr_set) {
        cudaFuncSetAttribute(k_mlp, cudaFuncAttributeMaxDynamicSharedMemorySize, MLP_SMEM);
        attr_set = true;
    }

    k_prep<<<144, 256>>>(qkv_w, proj_w, fc1_w, fc2_w);
    k_qkvln<<<NTOK / 128, 256>>>(x, n1g, n1b, qkv_b, p_qkv);
    k_attn<<<dim3(NWIN, HEADS), 128>>>(0);
    k_proj<<<NTOK / 64, 256>>>(p_att, proj_b, x, p_x2, p_h2, n2g, n2b);
    k_mlp<<<NTOK / 128, 256, MLP_SMEM>>>(p_h2, fc1_b, fc2_b, p_x2, out);
}